// round 11
// baseline (speedup 1.0000x reference)
#include <cuda_runtime.h>
#include <cuda_bf16.h>
#include <cstdint>

#define TABLE_SIZE (1u << 19)
#define HASH_MASK  (TABLE_SIZE - 1u)
#define PRIME1     2654435761u
#define NTH        256          // 128 consumer (4 warps) + 128 producer
#define NCONS      128
#define PTS        64

__device__ __constant__ float RES_TAB[16] = {
    16.f, 20.f, 25.f, 32.f, 40.f, 50.f, 64.f, 80.f,
    101.f, 128.f, 161.f, 203.f, 256.f, 322.f, 406.f, 512.f
};

// ---- smem layout (bytes). Strides 528B / 112B are ldmatrix conflict-free ----
#define WS_BIG   528
#define WS_SMALL 112
#define W1T_OFF  0               // [256 n][264] bf16 : 135168
#define W0T_OFF  135168          // [256 n][56]  bf16 : 28672
#define X_OFF    163840          // 2 x [64 m][56] bf16 : 14336
#define X_BUFSZ  7168
#define ACT_OFF  178176          // [64 m][264] bf16 : 33792
#define B0_OFF   211968          // 256 f32
#define B1_OFF   212992          // 256 f32
#define W2S_OFF  214016          // [256 n][4] f32 : 4096 (w2s[n*4+c], [3]=pad)
#define B2S_OFF  218112          // 4 f32
#define RED_OFF  218128          // [64 r][3 c][4 w] f32 : 3072
#define SMEM_BYTES 221200

// named barriers
#define BAR_FULL0   1
#define BAR_FULL1   2
#define BAR_EMPTY0  3
#define BAR_EMPTY1  4
#define BAR_CONS    5

__device__ __forceinline__ void bar_sync(int id, int cnt) {
    asm volatile("bar.sync %0, %1;" :: "r"(id), "r"(cnt) : "memory");
}
__device__ __forceinline__ void bar_arrive(int id, int cnt) {
    asm volatile("bar.arrive %0, %1;" :: "r"(id), "r"(cnt) : "memory");
}
__device__ __forceinline__ uint32_t smem_u32(const void* p) {
    uint32_t a;
    asm("{ .reg .u64 t; cvta.to.shared.u64 t, %1; cvt.u32.u64 %0, t; }" : "=r"(a) : "l"(p));
    return a;
}
__device__ __forceinline__ void ldm_x4(uint32_t* r, uint32_t addr) {
    asm volatile("ldmatrix.sync.aligned.m8n8.x4.shared.b16 {%0,%1,%2,%3}, [%4];"
        : "=r"(r[0]), "=r"(r[1]), "=r"(r[2]), "=r"(r[3]) : "r"(addr));
}
__device__ __forceinline__ void mma_bf16(float* d, const uint32_t* a, const uint32_t* b) {
    asm volatile("mma.sync.aligned.m16n8k16.row.col.f32.bf16.bf16.f32 "
        "{%0,%1,%2,%3}, {%4,%5,%6,%7}, {%8,%9}, {%0,%1,%2,%3};"
        : "+f"(d[0]), "+f"(d[1]), "+f"(d[2]), "+f"(d[3])
        : "r"(a[0]), "r"(a[1]), "r"(a[2]), "r"(a[3]), "r"(b[0]), "r"(b[1]));
}
__device__ __forceinline__ uint32_t packbf(float lo, float hi) {
    __nv_bfloat162 h = __floats2bfloat162_rn(lo, hi);
    return *reinterpret_cast<uint32_t*>(&h);
}

extern "C" __global__ void __launch_bounds__(NTH, 1)
ngp_wide_kernel(const float* __restrict__ coords,
                const float* __restrict__ emb,
                const float* __restrict__ W0, const float* __restrict__ b0,
                const float* __restrict__ W1, const float* __restrict__ b1,
                const float* __restrict__ W2, const float* __restrict__ b2,
                float* __restrict__ out, int npts)
{
    extern __shared__ char smem[];
    const uint32_t sb = smem_u32(smem);
    const int t = threadIdx.x;
    const int lane = t & 31;
    const int w = t >> 5;

    // ---- one-time weight staging ----
    for (int i = t; i < 7168; i += NTH) ((uint32_t*)(smem + W0T_OFF))[i] = 0;
    __syncthreads();
    for (int i = t; i < 256 * 256; i += NTH) {
        const int k = i >> 8, n = i & 255;
        *(__nv_bfloat16*)(smem + W1T_OFF + n * WS_BIG + k * 2) = __float2bfloat16(W1[i]);
    }
    for (int i = t; i < 34 * 256; i += NTH) {
        const int k = i >> 8, n = i & 255;
        *(__nv_bfloat16*)(smem + W0T_OFF + n * WS_SMALL + k * 2) = __float2bfloat16(W0[i]);
    }
    float* b0s = (float*)(smem + B0_OFF);
    float* b1s = (float*)(smem + B1_OFF);
    float* w2s = (float*)(smem + W2S_OFF);
    float* b2s = (float*)(smem + B2S_OFF);
    for (int i = t; i < 256; i += NTH) {
        b0s[i] = b0[i];
        b1s[i] = b1[i];
        w2s[i * 4 + 0] = W2[i * 3 + 0];
        w2s[i * 4 + 1] = W2[i * 3 + 1];
        w2s[i * 4 + 2] = W2[i * 3 + 2];
        w2s[i * 4 + 3] = 0.f;
    }
    if (t < 3) b2s[t] = b2[t];
    __syncthreads();

    const int ntiles = (npts + PTS - 1) / PTS;

    if (t >= NCONS) {
        // ============ PRODUCERS: encode (2 threads / point, 8 levels) =======
        const int tp = t - NCONS;        // 0..127
        const int p  = tp >> 1;          // point 0..63
        const int g  = tp & 1;           // half: 8 levels each
        int iter = 0;
        for (int tile = blockIdx.x; tile < ntiles; tile += gridDim.x, iter++) {
            const int b = iter & 1;
            if (iter >= 2) bar_sync(BAR_EMPTY0 + b, NTH);

            const int gp = tile * PTS + p;
            float2 c = make_float2(0.f, 0.f);
            if (gp < npts) c = ((const float2*)coords)[gp];
            const float x = fminf(fmaxf(c.x, -1.f), 1.f);
            const float y = fminf(fmaxf(c.y, -1.f), 1.f);
            char* xrow = smem + X_OFF + b * X_BUFSZ + p * WS_SMALL;

            if (g == 0) {
                *(uint32_t*)xrow = packbf(x, y);
            } else {      // zero pad k = 34..47
                #pragma unroll
                for (int z = 0; z < 7; z++) *(uint32_t*)(xrow + 68 + 4 * z) = 0;
            }
            #pragma unroll
            for (int li = 0; li < 8; li++) {
                const int l = g * 8 + li;
                const float res  = RES_TAB[l];
                const float grid = 2.0f / res;
                const float fx = floorf((x + 1.0f) / grid);
                const float fy = floorf((y + 1.0f) / grid);
                const float wx = (x - (fx * grid - 1.0f)) / grid;
                const float wy = (y - (fy * grid - 1.0f)) / grid;
                const unsigned bx = (unsigned)(int)fx;
                const unsigned by = (unsigned)(int)fy;
                const unsigned hy0 = by * PRIME1;
                const unsigned hy1 = (by + 1u) * PRIME1;
                const float2* tabl = (const float2*)emb + (size_t)l * TABLE_SIZE;
                const float2 e00 = tabl[(bx ^ hy0) & HASH_MASK];
                const float2 e01 = tabl[(bx ^ hy1) & HASH_MASK];
                const float2 e10 = tabl[((bx + 1u) ^ hy0) & HASH_MASK];
                const float2 e11 = tabl[((bx + 1u) ^ hy1) & HASH_MASK];
                const float omx = 1.f - wx, omy = 1.f - wy;
                const float f0 = (e00.x * omx + e10.x * wx) * omy + (e01.x * omx + e11.x * wx) * wy;
                const float f1 = (e00.y * omx + e10.y * wx) * omy + (e01.y * omx + e11.y * wx) * wy;
                *(uint32_t*)(xrow + (2 + 2 * l) * 2) = packbf(f0, f1);
            }
            bar_arrive(BAR_FULL0 + b, NTH);
        }
    } else {
        // ============ CONSUMERS: 4 warps, each m64 x n64 ====================
        const int arow  = (lane & 7) + ((lane >> 3) & 1) * 8;
        const int akoff = (lane >> 4) * 8;
        const int bgrp  = ((lane >> 4) << 3) + (lane & 7);   // B ldm_x4: 2 n-tiles/op
        const int bk16  = ((lane >> 3) & 1) * 16;
        const int nbase = w * 64;
        const int kbase = w * 4;          // dephased k-start per warp

        const uint32_t xlane0 = sb + X_OFF   + arow * WS_SMALL + akoff * 2;
        const uint32_t alane  = sb + ACT_OFF + arow * WS_BIG   + akoff * 2;
        const uint32_t w0lane = sb + W0T_OFF + (nbase + bgrp) * WS_SMALL + bk16;
        const uint32_t w1lane = sb + W1T_OFF + (nbase + bgrp) * WS_BIG   + bk16;

        float* red = (float*)(smem + RED_OFF);

        int iter = 0;
        for (int tile = blockIdx.x; tile < ntiles; tile += gridDim.x, iter++) {
            const int b = iter & 1;
            bar_sync(BAR_FULL0 + b, NTH);               // encode(tile) done

            float acc[4][8][4];     // [m-tile][n-tile][frag]
            #pragma unroll
            for (int i = 0; i < 4; i++)
                #pragma unroll
                for (int j = 0; j < 8; j++)
                    #pragma unroll
                    for (int q = 0; q < 4; q++) acc[i][j][q] = 0.f;

            // ---------- layer 0: [64,48] @ W0t ----------
            {
                const uint32_t xl = xlane0 + b * X_BUFSZ;
                #pragma unroll
                for (int ks = 0; ks < 3; ks++) {
                    uint32_t a[4][4], bb[4][4];
                    #pragma unroll
                    for (int i = 0; i < 4; i++)
                        ldm_x4(a[i], xl + i * 16 * WS_SMALL + ks * 32);
                    #pragma unroll
                    for (int jj = 0; jj < 4; jj++)
                        ldm_x4(bb[jj], w0lane + jj * 16 * WS_SMALL + ks * 32);
                    #pragma unroll
                    for (int i = 0; i < 4; i++)
                        #pragma unroll
                        for (int jj = 0; jj < 4; jj++) {
                            mma_bf16(acc[i][2 * jj],     a[i], bb[jj]);
                            mma_bf16(acc[i][2 * jj + 1], a[i], bb[jj] + 2);
                        }
                }
            }
            // epi0: relu + bias -> ACT
            #pragma unroll
            for (int i = 0; i < 4; i++) {
                const int r0 = i * 16 + (lane >> 2);
                #pragma unroll
                for (int j = 0; j < 8; j++) {
                    const int c = nbase + j * 8 + (lane & 3) * 2;
                    const float bx = b0s[c], by = b0s[c + 1];
                    *(uint32_t*)(smem + ACT_OFF + r0 * WS_BIG + c * 2) =
                        packbf(fmaxf(acc[i][j][0] + bx, 0.f), fmaxf(acc[i][j][1] + by, 0.f));
                    *(uint32_t*)(smem + ACT_OFF + (r0 + 8) * WS_BIG + c * 2) =
                        packbf(fmaxf(acc[i][j][2] + bx, 0.f), fmaxf(acc[i][j][3] + by, 0.f));
                }
            }
            bar_sync(BAR_CONS, NCONS);                  // full ACT visible
            bar_arrive(BAR_EMPTY0 + b, NTH);            // X buffer free

            // ---------- layer 1: [64,256] @ W1t, depth-2 prefetch, dephased ----
            #pragma unroll
            for (int i = 0; i < 4; i++)
                #pragma unroll
                for (int j = 0; j < 8; j++)
                    #pragma unroll
                    for (int q = 0; q < 4; q++) acc[i][j][q] = 0.f;
            {
                uint32_t aF[2][4][4], bF[2][4][4];
                {
                    const int ks0 = kbase & 15;
                    #pragma unroll
                    for (int i = 0; i < 4; i++)
                        ldm_x4(aF[0][i], alane + i * 16 * WS_BIG + ks0 * 32);
                    #pragma unroll
                    for (int jj = 0; jj < 4; jj++)
                        ldm_x4(bF[0][jj], w1lane + jj * 16 * WS_BIG + ks0 * 32);
                }
                #pragma unroll
                for (int it = 0; it < 16; it++) {
                    const int cur = it & 1, nxt = cur ^ 1;
                    if (it < 15) {
                        const int ksn = (kbase + it + 1) & 15;
                        #pragma unroll
                        for (int i = 0; i < 4; i++)
                            ldm_x4(aF[nxt][i], alane + i * 16 * WS_BIG + ksn * 32);
                        #pragma unroll
                        for (int jj = 0; jj < 4; jj++)
                            ldm_x4(bF[nxt][jj], w1lane + jj * 16 * WS_BIG + ksn * 32);
                    }
                    #pragma unroll
                    for (int i = 0; i < 4; i++)
                        #pragma unroll
                        for (int jj = 0; jj < 4; jj++) {
                            mma_bf16(acc[i][2 * jj],     aF[cur][i], bF[cur][jj]);
                            mma_bf16(acc[i][2 * jj + 1], aF[cur][i], bF[cur][jj] + 2);
                        }
                }
            }

            // ---------- fused layer 2: relu(acc+b1) . W2, smem-loaded weights ---
            {
                float zac[4][2][3];
                #pragma unroll
                for (int i = 0; i < 4; i++)
                    #pragma unroll
                    for (int rh = 0; rh < 2; rh++)
                        #pragma unroll
                        for (int c = 0; c < 3; c++) zac[i][rh][c] = 0.f;

                #pragma unroll
                for (int j = 0; j < 8; j++) {
                    const int np = nbase + j * 8 + (lane & 3) * 2;
                    const float b1lo = b1s[np], b1hi = b1s[np + 1];
                    const float4 w2lo = *(const float4*)(w2s + np * 4);
                    const float4 w2hi = *(const float4*)(w2s + (np + 1) * 4);
                    #pragma unroll
                    for (int i = 0; i < 4; i++)
                        #pragma unroll
                        for (int rh = 0; rh < 2; rh++) {
                            const float vlo = fmaxf(acc[i][j][2 * rh]     + b1lo, 0.f);
                            const float vhi = fmaxf(acc[i][j][2 * rh + 1] + b1hi, 0.f);
                            zac[i][rh][0] += vlo * w2lo.x + vhi * w2hi.x;
                            zac[i][rh][1] += vlo * w2lo.y + vhi * w2hi.y;
                            zac[i][rh][2] += vlo * w2lo.z + vhi * w2hi.z;
                        }
                }
                // quad reduce over lane bits 0,1 (col groups)
                #pragma unroll
                for (int i = 0; i < 4; i++)
                    #pragma unroll
                    for (int rh = 0; rh < 2; rh++)
                        #pragma unroll
                        for (int c = 0; c < 3; c++) {
                            float v = zac[i][rh][c];
                            v += __shfl_xor_sync(0xffffffffu, v, 1);
                            v += __shfl_xor_sync(0xffffffffu, v, 2);
                            zac[i][rh][c] = v;
                        }
                if ((lane & 3) == 0) {
                    #pragma unroll
                    for (int i = 0; i < 4; i++) {
                        const int r0 = i * 16 + (lane >> 2);
                        #pragma unroll
                        for (int rh = 0; rh < 2; rh++)
                            #pragma unroll
                            for (int c = 0; c < 3; c++)
                                red[(r0 + 8 * rh) * 12 + c * 4 + w] = zac[i][rh][c];
                    }
                }
            }
            bar_sync(BAR_CONS, NCONS);                  // red staged

            // ---------- final: sum 4 warps, sigmoid, store (192 outputs) ------
            #pragma unroll
            for (int pass = 0; pass < 2; pass++) {
                const int idx = t + pass * NCONS;
                if (idx < PTS * 3) {
                    const int r = idx / 3, c = idx - 3 * (idx / 3);
                    float s = b2s[c];
                    #pragma unroll
                    for (int w4 = 0; w4 < 4; w4++) s += red[r * 12 + c * 4 + w4];
                    const long gi = (long)tile * (PTS * 3) + idx;
                    if (gi < (long)npts * 3) out[gi] = 1.f / (1.f + __expf(-s));
                }
            }
        }
    }
}

extern "C" void kernel_launch(void* const* d_in, const int* in_sizes, int n_in,
                              void* d_out, int out_size)
{
    const float* coords = (const float*)d_in[0];
    const float* emb    = (const float*)d_in[1];
    const float* W0     = (const float*)d_in[2];
    const float* b0     = (const float*)d_in[3];
    const float* W1     = (const float*)d_in[4];
    const float* b1     = (const float*)d_in[5];
    const float* W2     = (const float*)d_in[6];
    const float* b2     = (const float*)d_in[7];
    float* out          = (float*)d_out;

    const int npts = in_sizes[0] / 2;

    int dev = 0, nsm = 148;
    cudaGetDevice(&dev);
    cudaDeviceGetAttribute(&nsm, cudaDevAttrMultiProcessorCount, dev);

    cudaFuncSetAttribute(ngp_wide_kernel,
                         cudaFuncAttributeMaxDynamicSharedMemorySize, SMEM_BYTES);

    ngp_wide_kernel<<<nsm, NTH, SMEM_BYTES>>>(coords, emb, W0, b0, W1, b1, W2, b2, out, npts);
}

// round 12
// speedup vs baseline: 1.0760x; 1.0760x over previous
#include <cuda_runtime.h>
#include <cuda_fp16.h>
#include <cstdint>

#define TABLE_SIZE (1u << 19)
#define HASH_MASK  (TABLE_SIZE - 1u)
#define PRIME1     2654435761u
#define NTH        384          // 256 consumer + 128 producer
#define NCONS      256
#define PTS        64

__device__ __constant__ float RES_TAB[16] = {
    16.f, 20.f, 25.f, 32.f, 40.f, 50.f, 64.f, 80.f,
    101.f, 128.f, 161.f, 203.f, 256.f, 322.f, 406.f, 512.f
};

// ---- smem layout (bytes) ----
#define WS_BIG   528
#define WS_SMALL 112
#define W1T_OFF  0               // [256 n][264] f16 : 135168
#define W0T_OFF  135168          // [256 n][56]  f16 : 28672
#define X_OFF    163840          // 2 x [64 m][56] f16 : 14336
#define X_BUFSZ  7168
#define ACT_OFF  178176          // [64 m][264] f16 : 33792
#define RED_OFF  211968          // [64 r][3 c][8 w] f32 : 6144
#define SMEM_BYTES 218112

// named barriers
#define BAR_FULL0   1
#define BAR_FULL1   2
#define BAR_EMPTY0  3
#define BAR_EMPTY1  4
#define BAR_CONS    5

__device__ __forceinline__ void bar_sync(int id, int cnt) {
    asm volatile("bar.sync %0, %1;" :: "r"(id), "r"(cnt) : "memory");
}
__device__ __forceinline__ void bar_arrive(int id, int cnt) {
    asm volatile("bar.arrive %0, %1;" :: "r"(id), "r"(cnt) : "memory");
}
__device__ __forceinline__ uint32_t smem_u32(const void* p) {
    uint32_t a;
    asm("{ .reg .u64 t; cvta.to.shared.u64 t, %1; cvt.u32.u64 %0, t; }" : "=r"(a) : "l"(p));
    return a;
}
__device__ __forceinline__ void ldm_x4(uint32_t* r, uint32_t addr) {
    asm volatile("ldmatrix.sync.aligned.m8n8.x4.shared.b16 {%0,%1,%2,%3}, [%4];"
        : "=r"(r[0]), "=r"(r[1]), "=r"(r[2]), "=r"(r[3]) : "r"(addr));
}
// f16 x f16 -> f16 accumulate: D/C are 2 regs (f16x2 pairs)
__device__ __forceinline__ void mma_f16h(uint32_t* d, const uint32_t* a, const uint32_t* b) {
    asm volatile("mma.sync.aligned.m16n8k16.row.col.f16.f16.f16.f16 "
        "{%0,%1}, {%2,%3,%4,%5}, {%6,%7}, {%0,%1};"
        : "+r"(d[0]), "+r"(d[1])
        : "r"(a[0]), "r"(a[1]), "r"(a[2]), "r"(a[3]), "r"(b[0]), "r"(b[1]));
}
__device__ __forceinline__ uint32_t packh(float lo, float hi) {
    __half2 h = __floats2half2_rn(lo, hi);
    return *reinterpret_cast<uint32_t*>(&h);
}
__device__ __forceinline__ uint32_t hmax2_zero(uint32_t v) {
    __half2 h = *reinterpret_cast<__half2*>(&v);
    __half2 z = __floats2half2_rn(0.f, 0.f);
    __half2 r = __hmax2(h, z);
    return *reinterpret_cast<uint32_t*>(&r);
}

extern "C" __global__ void __launch_bounds__(NTH, 1)
ngp_f16_kernel(const float* __restrict__ coords,
               const float* __restrict__ emb,
               const float* __restrict__ W0, const float* __restrict__ b0,
               const float* __restrict__ W1, const float* __restrict__ b1,
               const float* __restrict__ W2, const float* __restrict__ b2,
               float* __restrict__ out, int npts)
{
    extern __shared__ char smem[];
    const uint32_t sb = smem_u32(smem);
    const int t = threadIdx.x;
    const int lane = t & 31;
    const int w = t >> 5;

    // ---- one-time weight staging (f16) ----
    for (int i = t; i < 7168; i += NTH) ((uint32_t*)(smem + W0T_OFF))[i] = 0;
    __syncthreads();
    for (int i = t; i < 256 * 256; i += NTH) {
        const int k = i >> 8, n = i & 255;
        *(__half*)(smem + W1T_OFF + n * WS_BIG + k * 2) = __float2half(W1[i]);
    }
    for (int i = t; i < 34 * 256; i += NTH) {
        const int k = i >> 8, n = i & 255;
        *(__half*)(smem + W0T_OFF + n * WS_SMALL + k * 2) = __float2half(W0[i]);
    }
    __syncthreads();

    const int ntiles = (npts + PTS - 1) / PTS;

    if (t >= NCONS) {
        // ============ PRODUCERS: encode (2 threads / point, 8 levels) =======
        const int tp = t - NCONS;        // 0..127
        const int p  = tp >> 1;          // point 0..63
        const int g  = tp & 1;           // half: 8 levels each
        int iter = 0;
        for (int tile = blockIdx.x; tile < ntiles; tile += gridDim.x, iter++) {
            const int b = iter & 1;
            if (iter >= 2) bar_sync(BAR_EMPTY0 + b, NTH);

            const int gp = tile * PTS + p;
            float2 c = make_float2(0.f, 0.f);
            if (gp < npts) c = ((const float2*)coords)[gp];
            const float x = fminf(fmaxf(c.x, -1.f), 1.f);
            const float y = fminf(fmaxf(c.y, -1.f), 1.f);
            char* xrow = smem + X_OFF + b * X_BUFSZ + p * WS_SMALL;

            if (g == 0) {
                *(uint32_t*)xrow = packh(x, y);
            } else {      // zero pad k = 34..47
                #pragma unroll
                for (int z = 0; z < 7; z++) *(uint32_t*)(xrow + 68 + 4 * z) = 0;
            }
            #pragma unroll
            for (int li = 0; li < 8; li++) {
                const int l = g * 8 + li;
                const float res  = RES_TAB[l];
                const float grid = 2.0f / res;
                const float fx = floorf((x + 1.0f) / grid);
                const float fy = floorf((y + 1.0f) / grid);
                const float wx = (x - (fx * grid - 1.0f)) / grid;
                const float wy = (y - (fy * grid - 1.0f)) / grid;
                const unsigned bx = (unsigned)(int)fx;
                const unsigned by = (unsigned)(int)fy;
                const unsigned hy0 = by * PRIME1;
                const unsigned hy1 = (by + 1u) * PRIME1;
                const float2* tabl = (const float2*)emb + (size_t)l * TABLE_SIZE;
                const float2 e00 = tabl[(bx ^ hy0) & HASH_MASK];
                const float2 e01 = tabl[(bx ^ hy1) & HASH_MASK];
                const float2 e10 = tabl[((bx + 1u) ^ hy0) & HASH_MASK];
                const float2 e11 = tabl[((bx + 1u) ^ hy1) & HASH_MASK];
                const float omx = 1.f - wx, omy = 1.f - wy;
                const float f0 = (e00.x * omx + e10.x * wx) * omy + (e01.x * omx + e11.x * wx) * wy;
                const float f1 = (e00.y * omx + e10.y * wx) * omy + (e01.y * omx + e11.y * wx) * wy;
                *(uint32_t*)(xrow + (2 + 2 * l) * 2) = packh(f0, f1);
            }
            bar_arrive(BAR_FULL0 + b, NTH);
        }
    } else {
        // ============ CONSUMERS: 8 warps, each m64 x n32 ====================
        const int arow  = (lane & 7) + ((lane >> 3) & 1) * 8;
        const int akoff = (lane >> 4) * 8;
        const int bgrp  = ((lane >> 4) << 3) + (lane & 7);
        const int bk16  = ((lane >> 3) & 1) * 16;
        const int nbase = w * 32;

        const uint32_t xlane0 = sb + X_OFF   + arow * WS_SMALL + akoff * 2;
        const uint32_t alane  = sb + ACT_OFF + arow * WS_BIG   + akoff * 2;
        const uint32_t w0lane = sb + W0T_OFF + (nbase + bgrp) * WS_SMALL + bk16;
        const uint32_t w1lane = sb + W1T_OFF + (nbase + bgrp) * WS_BIG   + bk16;

        // preload biases (as f16x2 C-operand init) and W2 for this thread's cols
        uint32_t b0p[4], b1p[4];
        float w2r[4][2][3];
        #pragma unroll
        for (int j = 0; j < 4; j++) {
            const int n = nbase + j * 8 + 2 * (lane & 3);
            b0p[j] = packh(b0[n], b0[n + 1]);
            b1p[j] = packh(b1[n], b1[n + 1]);
            #pragma unroll
            for (int c = 0; c < 3; c++) {
                w2r[j][0][c] = W2[n * 3 + c];
                w2r[j][1][c] = W2[(n + 1) * 3 + c];
            }
        }
        const int fr = t / 3;
        const int fc = t - 3 * fr;
        const float b2v = (t < 192) ? b2[fc] : 0.f;
        float* red = (float*)(smem + RED_OFF);

        int iter = 0;
        for (int tile = blockIdx.x; tile < ntiles; tile += gridDim.x, iter++) {
            const int b = iter & 1;
            bar_sync(BAR_FULL0 + b, NTH);               // encode(tile) done

            uint32_t acc[4][4][2];    // f16x2 accumulators, C preloaded with bias
            #pragma unroll
            for (int i = 0; i < 4; i++)
                #pragma unroll
                for (int j = 0; j < 4; j++) {
                    acc[i][j][0] = b0p[j];
                    acc[i][j][1] = b0p[j];
                }

            // ---------- layer 0: [64,48] @ W0t ----------
            {
                const uint32_t xl = xlane0 + b * X_BUFSZ;
                #pragma unroll
                for (int ks = 0; ks < 3; ks++) {
                    uint32_t a[4][4], bb[2][4];
                    #pragma unroll
                    for (int i = 0; i < 4; i++)
                        ldm_x4(a[i], xl + i * 16 * WS_SMALL + ks * 32);
                    #pragma unroll
                    for (int jj = 0; jj < 2; jj++)
                        ldm_x4(bb[jj], w0lane + jj * 16 * WS_SMALL + ks * 32);
                    #pragma unroll
                    for (int i = 0; i < 4; i++)
                        #pragma unroll
                        for (int jj = 0; jj < 2; jj++) {
                            mma_f16h(acc[i][2 * jj],     a[i], bb[jj]);
                            mma_f16h(acc[i][2 * jj + 1], a[i], bb[jj] + 2);
                        }
                }
            }
            // epi0: relu (hmax2) -> ACT, already f16x2 packed
            #pragma unroll
            for (int i = 0; i < 4; i++) {
                const int r0 = i * 16 + (lane >> 2);
                #pragma unroll
                for (int j = 0; j < 4; j++) {
                    const int c = nbase + j * 8 + (lane & 3) * 2;
                    *(uint32_t*)(smem + ACT_OFF + r0 * WS_BIG + c * 2)       = hmax2_zero(acc[i][j][0]);
                    *(uint32_t*)(smem + ACT_OFF + (r0 + 8) * WS_BIG + c * 2) = hmax2_zero(acc[i][j][1]);
                }
            }
            bar_sync(BAR_CONS, NCONS);                  // full ACT visible
            bar_arrive(BAR_EMPTY0 + b, NTH);            // X buffer free

            // ---------- layer 1: [64,256] @ W1t ----------
            #pragma unroll
            for (int i = 0; i < 4; i++)
                #pragma unroll
                for (int j = 0; j < 4; j++) {
                    acc[i][j][0] = b1p[j];
                    acc[i][j][1] = b1p[j];
                }
            #pragma unroll
            for (int ks = 0; ks < 16; ks++) {
                uint32_t a[4][4], bb[2][4];
                #pragma unroll
                for (int i = 0; i < 4; i++)
                    ldm_x4(a[i], alane + i * 16 * WS_BIG + ks * 32);
                #pragma unroll
                for (int jj = 0; jj < 2; jj++)
                    ldm_x4(bb[jj], w1lane + jj * 16 * WS_BIG + ks * 32);
                #pragma unroll
                for (int i = 0; i < 4; i++)
                    #pragma unroll
                    for (int jj = 0; jj < 2; jj++) {
                        mma_f16h(acc[i][2 * jj],     a[i], bb[jj]);
                        mma_f16h(acc[i][2 * jj + 1], a[i], bb[jj] + 2);
                    }
            }

            // ---------- fused layer 2: relu in f16, FMA in f32 ----------
            #pragma unroll
            for (int i = 0; i < 4; i++) {
                float pacc[2][3];
                #pragma unroll
                for (int rh = 0; rh < 2; rh++)
                    #pragma unroll
                    for (int c = 0; c < 3; c++) pacc[rh][c] = 0.f;

                #pragma unroll
                for (int j = 0; j < 4; j++) {
                    #pragma unroll
                    for (int rh = 0; rh < 2; rh++) {
                        const uint32_t hr = hmax2_zero(acc[i][j][rh]);
                        const __half2 h2 = *reinterpret_cast<const __half2*>(&hr);
                        const float2 f = __half22float2(h2);
                        #pragma unroll
                        for (int c = 0; c < 3; c++)
                            pacc[rh][c] += f.x * w2r[j][0][c] + f.y * w2r[j][1][c];
                    }
                }
                // quad reduce over lane bits 0,1 (col-pair groups)
                #pragma unroll
                for (int rh = 0; rh < 2; rh++)
                    #pragma unroll
                    for (int c = 0; c < 3; c++) {
                        float v = pacc[rh][c];
                        v += __shfl_xor_sync(0xffffffffu, v, 1);
                        v += __shfl_xor_sync(0xffffffffu, v, 2);
                        pacc[rh][c] = v;
                    }
                if ((lane & 3) == 0) {
                    const int r0 = i * 16 + (lane >> 2);
                    #pragma unroll
                    for (int rh = 0; rh < 2; rh++)
                        #pragma unroll
                        for (int c = 0; c < 3; c++)
                            red[(r0 + 8 * rh) * 24 + c * 8 + w] = pacc[rh][c];
                }
            }
            bar_sync(BAR_CONS, NCONS);                  // red staged

            // ---------- final: sum 8 warps, sigmoid, store ----------
            if (t < 192) {
                float s = b2v;
                #pragma unroll
                for (int w8 = 0; w8 < 8; w8++) s += red[fr * 24 + fc * 8 + w8];
                const int gp = tile * PTS + fr;
                if (gp < npts) out[gp * 3 + fc] = 1.f / (1.f + __expf(-s));
            }
        }
    }
}

extern "C" void kernel_launch(void* const* d_in, const int* in_sizes, int n_in,
                              void* d_out, int out_size)
{
    const float* coords = (const float*)d_in[0];
    const float* emb    = (const float*)d_in[1];
    const float* W0     = (const float*)d_in[2];
    const float* b0     = (const float*)d_in[3];
    const float* W1     = (const float*)d_in[4];
    const float* b1     = (const float*)d_in[5];
    const float* W2     = (const float*)d_in[6];
    const float* b2     = (const float*)d_in[7];
    float* out          = (float*)d_out;

    const int npts = in_sizes[0] / 2;

    int dev = 0, nsm = 148;
    cudaGetDevice(&dev);
    cudaDeviceGetAttribute(&nsm, cudaDevAttrMultiProcessorCount, dev);

    cudaFuncSetAttribute(ngp_f16_kernel,
                         cudaFuncAttributeMaxDynamicSharedMemorySize, SMEM_BYTES);

    ngp_f16_kernel<<<nsm, NTH, SMEM_BYTES>>>(coords, emb, W0, b0, W1, b1, W2, b2, out, npts);
}